// round 15
// baseline (speedup 1.0000x reference)
#include <cuda_runtime.h>
#include <math.h>

#define BI 256
#define BC 256
#define TT 64
#define DD 1024
#define DR 256
#define LREG 36
#define EPSN 1e-8f
#define KSPLIT 4
#define KC (DD / KSPLIT)  // 256

// ---------------- scratch (no allocations allowed) ----------------
__device__ float g_cap_v[BC * DD];
__device__ float g_w[BC * 3];
__device__ float g_t[BC];
__device__ float g_P[BI * 3 * DD];
__device__ float g_CC[BI * 3 * DD];
__device__ float g_Spart[KSPLIT][BI * 3 * BC];
__device__ float g_qpart[2 * 3 * DD];  // e-split partials of q[k] = red_w^T @ proj_w[k]
__device__ float g_c[3];               // c[k] = red_b . proj_w[k] + proj_b[k]

// ---------------- f32x2 packed FMA helpers ----------------
static __device__ __forceinline__ void fma2(unsigned long long& d,
                                            unsigned long long a,
                                            unsigned long long b) {
    asm("fma.rn.f32x2 %0, %1, %2, %0;" : "+l"(d) : "l"(a), "l"(b));
}
static __device__ __forceinline__ float2 unpk(unsigned long long v) {
    float2 r;
    asm("mov.b64 {%0, %1}, %2;" : "=f"(r.x), "=f"(r.y) : "l"(v));
    return r;
}
static __device__ __forceinline__ float dot4(float4 a, float4 b) {
    return a.x * b.x + a.y * b.y + a.z * b.z + a.w * b.w;
}

// ---------------- kernel 0: q[k] = red_w^T @ proj_w[k]  (e-split x2), c[k] ----------------
// grid 8 x 256: blockIdx>>2 selects e-half, blockIdx&3 selects d-quarter.
__global__ __launch_bounds__(256) void prep_q(const float* __restrict__ red_w,
                                              const float* __restrict__ red_b,
                                              const float* __restrict__ proj_w,
                                              const float* __restrict__ proj_b,
                                              float* __restrict__ qpart,
                                              float* __restrict__ c) {
    const int part = blockIdx.x >> 2;
    const int d = (blockIdx.x & 3) * 256 + threadIdx.x;
    const int e0 = part * (DR / 2);
    float a0 = 0.f, a1 = 0.f, a2 = 0.f;
#pragma unroll 16
    for (int e = e0; e < e0 + DR / 2; e++) {
        float r = __ldg(red_w + (size_t)e * DD + d);
        a0 += r * proj_w[e];
        a1 += r * proj_w[DR + e];
        a2 += r * proj_w[2 * DR + e];
    }
    qpart[part * 3 * DD + 0 * DD + d] = a0;
    qpart[part * 3 * DD + 1 * DD + d] = a1;
    qpart[part * 3 * DD + 2 * DD + d] = a2;

    if (blockIdx.x == 0 && threadIdx.x < 32) {
        int l = threadIdx.x;
        float c0 = 0.f, c1 = 0.f, c2 = 0.f;
#pragma unroll
        for (int j = 0; j < DR / 32; j++) {
            int e = l + j * 32;
            float rb = red_b[e];
            c0 += rb * proj_w[e];
            c1 += rb * proj_w[DR + e];
            c2 += rb * proj_w[2 * DR + e];
        }
#pragma unroll
        for (int off = 16; off > 0; off >>= 1) {
            c0 += __shfl_xor_sync(0xffffffffu, c0, off);
            c1 += __shfl_xor_sync(0xffffffffu, c1, off);
            c2 += __shfl_xor_sync(0xffffffffu, c2, off);
        }
        if (l == 0) {
            c[0] = c0 + proj_b[0];
            c[1] = c1 + proj_b[1];
            c[2] = c2 + proj_b[2];
        }
    }
}

// ---------------- fused input reductions + softmax filter ----------------
// blocks [0, BC)     : caption masked mean -> cap_v, w[b] (softmax), t[b]
// blocks [BC, BC+BI) : image region pooling (3 shifted sums / L)
__global__ __launch_bounds__(256) void pre_reduce(const float* __restrict__ cap,
                                                  const int* __restrict__ lens,
                                                  const float* __restrict__ img,
                                                  const float* __restrict__ conv_b,
                                                  const float* __restrict__ qpart,
                                                  const float* __restrict__ c,
                                                  float* __restrict__ cap_v,
                                                  float* __restrict__ w_out,
                                                  float* __restrict__ t_out,
                                                  float* __restrict__ P) {
    int tid = threadIdx.x;
    if (blockIdx.x < BC) {
        int b = blockIdx.x;
        int len = __ldg(lens + b);
        const float4* row = (const float4*)(cap + (size_t)b * TT * DD);
        float4 acc = make_float4(0.f, 0.f, 0.f, 0.f);
#pragma unroll 8
        for (int t = 0; t < len; t++) {
            float4 v = row[t * (DD / 4) + tid];
            acc.x += v.x; acc.y += v.y; acc.z += v.z; acc.w += v.w;
        }
        float inv = 1.0f / (float)len;
        acc.x *= inv; acc.y *= inv; acc.z *= inv; acc.w *= inv;

        // per-thread partials: norm, 3 logit dots (two e-halves of q), conv_b dot
        const float4* qA = (const float4*)qpart;                // [3][DD/4]
        const float4* qB = (const float4*)(qpart + 3 * DD);
        const float4* cb4 = (const float4*)conv_b;
        float ss = dot4(acc, acc);
        float p0 = dot4(acc, qA[0 * (DD / 4) + tid]) + dot4(acc, qB[0 * (DD / 4) + tid]);
        float p1 = dot4(acc, qA[1 * (DD / 4) + tid]) + dot4(acc, qB[1 * (DD / 4) + tid]);
        float p2 = dot4(acc, qA[2 * (DD / 4) + tid]) + dot4(acc, qB[2 * (DD / 4) + tid]);
        float tb = dot4(acc, cb4[tid]);
#pragma unroll
        for (int off = 16; off > 0; off >>= 1) {
            ss += __shfl_xor_sync(0xffffffffu, ss, off);
            p0 += __shfl_xor_sync(0xffffffffu, p0, off);
            p1 += __shfl_xor_sync(0xffffffffu, p1, off);
            p2 += __shfl_xor_sync(0xffffffffu, p2, off);
            tb += __shfl_xor_sync(0xffffffffu, tb, off);
        }
        __shared__ float sw[8][5];
        __shared__ float sinv;
        if ((tid & 31) == 0) {
            int w = tid >> 5;
            sw[w][0] = ss; sw[w][1] = p0; sw[w][2] = p1; sw[w][3] = p2; sw[w][4] = tb;
        }
        __syncthreads();
        if (tid == 0) {
            float tss = 0.f, tp0 = 0.f, tp1 = 0.f, tp2 = 0.f, ttb = 0.f;
#pragma unroll
            for (int w = 0; w < 8; w++) {
                tss += sw[w][0]; tp0 += sw[w][1]; tp1 += sw[w][2];
                tp2 += sw[w][3]; ttb += sw[w][4];
            }
            float si = 1.0f / (sqrtf(tss) + EPSN);
            sinv = si;
            float l0 = tp0 + c[0], l1 = tp1 + c[1], l2 = tp2 + c[2];
            float mx = fmaxf(l0, fmaxf(l1, l2));
            float e0 = expf(l0 - mx), e1 = expf(l1 - mx), e2 = expf(l2 - mx);
            float einv = 1.0f / (e0 + e1 + e2);
            w_out[b * 3 + 0] = e0 * einv;
            w_out[b * 3 + 1] = e1 * einv;
            w_out[b * 3 + 2] = e2 * einv;
            t_out[b] = ttb * si;  // conv_b . cap_v[b]
        }
        __syncthreads();
        float si = sinv;
        float4 nv = make_float4(acc.x * si, acc.y * si, acc.z * si, acc.w * si);
        ((float4*)(cap_v + (size_t)b * DD))[tid] = nv;
    } else {
        int i = blockIdx.x - BC;
        const float4* base = (const float4*)(img + (size_t)i * LREG * DD);
        float4 s = make_float4(0.f, 0.f, 0.f, 0.f);
        float4 r0 = make_float4(0.f, 0.f, 0.f, 0.f);
        float4 r35 = make_float4(0.f, 0.f, 0.f, 0.f);
#pragma unroll 4
        for (int t = 0; t < LREG; t++) {
            float4 v = base[t * (DD / 4) + tid];
            if (t == 0) r0 = v;
            if (t == LREG - 1) r35 = v;
            s.x += v.x; s.y += v.y; s.z += v.z; s.w += v.w;
        }
        const float invL = 1.0f / (float)LREG;
        float4 p0 = make_float4((s.x - r35.x) * invL, (s.y - r35.y) * invL,
                                (s.z - r35.z) * invL, (s.w - r35.w) * invL);
        float4 p1 = make_float4(s.x * invL, s.y * invL, s.z * invL, s.w * invL);
        float4 p2 = make_float4((s.x - r0.x) * invL, (s.y - r0.y) * invL,
                                (s.z - r0.z) * invL, (s.w - r0.w) * invL);
        ((float4*)(P + (size_t)(i * 3 + 0) * DD))[tid] = p0;
        ((float4*)(P + (size_t)(i * 3 + 1) * DD))[tid] = p1;
        ((float4*)(P + (size_t)(i * 3 + 2) * DD))[tid] = p2;
    }
}

// ---------------- GEMM: C[m,n] = sum_k A[m,k]*B[n,k] (A: MxK, B: NxK, row-major) ----------------
// 32x64 tile, BK=32, 128 threads, 4x4 micro-tile via packed fma.rn.f32x2.
// 2-stage smem double buffering (one __syncthreads per BK=32 chunk); optional
// split-K along gridDim.z into per-partition output buffers (Cz = C + z*M*N),
// exact & deterministic.
__global__ __launch_bounds__(128) void gemm_s(const float* __restrict__ A,
                                              const float* __restrict__ B,
                                              float* __restrict__ C,
                                              int M, int N, int K, int KCsz) {
    __shared__ __align__(16) float2 As2[2][32][34];  // 34*8=272B row stride
    __shared__ __align__(16) float Bs[2][32][68];    // 68*4=272B row stride
    const int bm = blockIdx.y * 32, bn = blockIdx.x * 64;
    const int kbase = blockIdx.z * KCsz;
    float* Cz = C + (size_t)blockIdx.z * M * N;
    const int tid = threadIdx.x;
    const int tn = tid & 15, tm = tid >> 4;  // tm 0..7
    const int n0 = tn * 4, m0 = tm * 4;
    const int lr = tid >> 2, lk = (tid & 3) * 4;  // lr 0..31; k-cols lk and lk+16

    unsigned long long acc[4][2];
#pragma unroll
    for (int i = 0; i < 4; i++) { acc[i][0] = 0ULL; acc[i][1] = 0ULL; }

    const float* Ap = A + (size_t)(bm + lr) * K + kbase + lk;
    const float* Bp0 = B + (size_t)(bn + lr) * K + kbase + lk;
    const float* Bp1 = B + (size_t)(bn + lr + 32) * K + kbase + lk;

    const int T = KCsz / 32;

    // prologue: fill buffer 0 (k-chunk 0)
    {
        float4 aA = *(const float4*)(Ap);
        float4 aB = *(const float4*)(Ap + 16);
        float4 b00 = *(const float4*)(Bp0);
        float4 b01 = *(const float4*)(Bp0 + 16);
        float4 b10 = *(const float4*)(Bp1);
        float4 b11 = *(const float4*)(Bp1 + 16);
        As2[0][lk + 0][lr] = make_float2(aA.x, aA.x);
        As2[0][lk + 1][lr] = make_float2(aA.y, aA.y);
        As2[0][lk + 2][lr] = make_float2(aA.z, aA.z);
        As2[0][lk + 3][lr] = make_float2(aA.w, aA.w);
        As2[0][lk + 16][lr] = make_float2(aB.x, aB.x);
        As2[0][lk + 17][lr] = make_float2(aB.y, aB.y);
        As2[0][lk + 18][lr] = make_float2(aB.z, aB.z);
        As2[0][lk + 19][lr] = make_float2(aB.w, aB.w);
        Bs[0][lk + 0][lr] = b00.x; Bs[0][lk + 1][lr] = b00.y;
        Bs[0][lk + 2][lr] = b00.z; Bs[0][lk + 3][lr] = b00.w;
        Bs[0][lk + 16][lr] = b01.x; Bs[0][lk + 17][lr] = b01.y;
        Bs[0][lk + 18][lr] = b01.z; Bs[0][lk + 19][lr] = b01.w;
        Bs[0][lk + 0][lr + 32] = b10.x; Bs[0][lk + 1][lr + 32] = b10.y;
        Bs[0][lk + 2][lr + 32] = b10.z; Bs[0][lk + 3][lr + 32] = b10.w;
        Bs[0][lk + 16][lr + 32] = b11.x; Bs[0][lk + 17][lr + 32] = b11.y;
        Bs[0][lk + 18][lr + 32] = b11.z; Bs[0][lk + 19][lr + 32] = b11.w;
    }
    __syncthreads();

    for (int t = 0; t < T; t++) {
        float4 aA, aB, b00, b01, b10, b11;
        if (t + 1 < T) {
            int off = (t + 1) * 32;
            aA = *(const float4*)(Ap + off);
            aB = *(const float4*)(Ap + off + 16);
            b00 = *(const float4*)(Bp0 + off);
            b01 = *(const float4*)(Bp0 + off + 16);
            b10 = *(const float4*)(Bp1 + off);
            b11 = *(const float4*)(Bp1 + off + 16);
        }
        const int buf = t & 1;
#pragma unroll
        for (int kk = 0; kk < 32; kk++) {
            ulonglong2 a01 = *(const ulonglong2*)&As2[buf][kk][m0];
            ulonglong2 a23 = *(const ulonglong2*)&As2[buf][kk][m0 + 2];
            ulonglong2 bq = *(const ulonglong2*)&Bs[buf][kk][n0];
            fma2(acc[0][0], a01.x, bq.x); fma2(acc[0][1], a01.x, bq.y);
            fma2(acc[1][0], a01.y, bq.x); fma2(acc[1][1], a01.y, bq.y);
            fma2(acc[2][0], a23.x, bq.x); fma2(acc[2][1], a23.x, bq.y);
            fma2(acc[3][0], a23.y, bq.x); fma2(acc[3][1], a23.y, bq.y);
        }
        if (t + 1 < T) {
            const int nb = (t + 1) & 1;
            As2[nb][lk + 0][lr] = make_float2(aA.x, aA.x);
            As2[nb][lk + 1][lr] = make_float2(aA.y, aA.y);
            As2[nb][lk + 2][lr] = make_float2(aA.z, aA.z);
            As2[nb][lk + 3][lr] = make_float2(aA.w, aA.w);
            As2[nb][lk + 16][lr] = make_float2(aB.x, aB.x);
            As2[nb][lk + 17][lr] = make_float2(aB.y, aB.y);
            As2[nb][lk + 18][lr] = make_float2(aB.z, aB.z);
            As2[nb][lk + 19][lr] = make_float2(aB.w, aB.w);
            Bs[nb][lk + 0][lr] = b00.x; Bs[nb][lk + 1][lr] = b00.y;
            Bs[nb][lk + 2][lr] = b00.z; Bs[nb][lk + 3][lr] = b00.w;
            Bs[nb][lk + 16][lr] = b01.x; Bs[nb][lk + 17][lr] = b01.y;
            Bs[nb][lk + 18][lr] = b01.z; Bs[nb][lk + 19][lr] = b01.w;
            Bs[nb][lk + 0][lr + 32] = b10.x; Bs[nb][lk + 1][lr + 32] = b10.y;
            Bs[nb][lk + 2][lr + 32] = b10.z; Bs[nb][lk + 3][lr + 32] = b10.w;
            Bs[nb][lk + 16][lr + 32] = b11.x; Bs[nb][lk + 17][lr + 32] = b11.y;
            Bs[nb][lk + 18][lr + 32] = b11.z; Bs[nb][lk + 19][lr + 32] = b11.w;
            __syncthreads();
        }
    }
#pragma unroll
    for (int i = 0; i < 4; i++) {
        float2 f0 = unpk(acc[i][0]);
        float2 f1 = unpk(acc[i][1]);
        float4 o = make_float4(f0.x, f0.y, f1.x, f1.y);
        *(float4*)(Cz + (size_t)(bm + m0 + i) * N + bn + n0) = o;
    }
}

// ---------------- fused kernel: per-image Gram + split-K sum + final similarity ----------------
__global__ __launch_bounds__(256) void final_kernel(const float* __restrict__ CC,
                                                    const float* __restrict__ conv_b,
                                                    const float* __restrict__ Spart,
                                                    const float* __restrict__ W,
                                                    const float* __restrict__ T_,
                                                    float* __restrict__ out) {
    int i = blockIdx.x;
    int tid = threadIdx.x;

    // --- Gram of {cc0, cc1, cc2, conv_b} over D=1024 (each thread: 4 dims) ---
    const float4* c0 = (const float4*)(CC + (size_t)(i * 3 + 0) * DD);
    const float4* c1 = (const float4*)(CC + (size_t)(i * 3 + 1) * DD);
    const float4* c2 = (const float4*)(CC + (size_t)(i * 3 + 2) * DD);
    const float4* cb = (const float4*)conv_b;
    float4 v0 = c0[tid], v1 = c1[tid], v2 = c2[tid], vb = cb[tid];
    float p[10];
    p[0] = dot4(v0, v0); p[1] = dot4(v0, v1); p[2] = dot4(v0, v2);
    p[3] = dot4(v0, vb); p[4] = dot4(v1, v1); p[5] = dot4(v1, v2);
    p[6] = dot4(v1, vb); p[7] = dot4(v2, v2); p[8] = dot4(v2, vb);
    p[9] = dot4(vb, vb);
#pragma unroll
    for (int q = 0; q < 10; q++) {
#pragma unroll
        for (int off = 16; off > 0; off >>= 1)
            p[q] += __shfl_xor_sync(0xffffffffu, p[q], off);
    }
    __shared__ float sp[8][10];
    if ((tid & 31) == 0) {
        int w = tid >> 5;
#pragma unroll
        for (int q = 0; q < 10; q++) sp[w][q] = p[q];
    }
    __syncthreads();
    __shared__ float sG[10];
    if (tid < 10) {
        float s = 0.f;
#pragma unroll
        for (int w = 0; w < 8; w++) s += sp[w][tid];
        sG[tid] = s;
    }
    __syncthreads();

    // --- final similarity: thread tid handles caption b = tid ---
    int b = tid;
    float w0 = W[b * 3 + 0], w1 = W[b * 3 + 1], w2 = W[b * 3 + 2];
    float s0 = 0.f, s1 = 0.f, s2 = 0.f;
#pragma unroll
    for (int z = 0; z < KSPLIT; z++) {
        const float* Sz = Spart + (size_t)z * (BI * 3 * BC);
        s0 += Sz[(size_t)(i * 3 + 0) * BC + b];
        s1 += Sz[(size_t)(i * 3 + 1) * BC + b];
        s2 += Sz[(size_t)(i * 3 + 2) * BC + b];
    }
    float num = w0 * s0 + w1 * s1 + w2 * s2 + T_[b];
    // G order: 00,01,02,0b,11,12,1b,22,2b,bb ; w_tilde = (w0,w1,w2,1)
    float quad = w0 * w0 * sG[0] + w1 * w1 * sG[4] + w2 * w2 * sG[7] + sG[9] +
                 2.0f * (w0 * w1 * sG[1] + w0 * w2 * sG[2] + w0 * sG[3] +
                         w1 * w2 * sG[5] + w1 * sG[6] + w2 * sG[8]);
    out[(size_t)i * BC + b] = num / (sqrtf(quad) + EPSN);
}

// ---------------- host launcher ----------------
extern "C" void kernel_launch(void* const* d_in, const int* in_sizes, int n_in,
                              void* d_out, int out_size) {
    const float* img = (const float*)d_in[0];
    const float* cap = (const float*)d_in[1];
    const int* lens = (const int*)d_in[2];
    const float* red_w = (const float*)d_in[3];
    const float* red_b = (const float*)d_in[4];
    const float* proj_w = (const float*)d_in[5];
    const float* proj_b = (const float*)d_in[6];
    const float* conv_w = (const float*)d_in[7];
    const float* conv_b = (const float*)d_in[8];
    float* out = (float*)d_out;

    float *capV, *W, *T_, *P, *CC, *SP, *QP, *Cc;
    cudaGetSymbolAddress((void**)&capV, g_cap_v);
    cudaGetSymbolAddress((void**)&W, g_w);
    cudaGetSymbolAddress((void**)&T_, g_t);
    cudaGetSymbolAddress((void**)&P, g_P);
    cudaGetSymbolAddress((void**)&CC, g_CC);
    cudaGetSymbolAddress((void**)&SP, g_Spart);
    cudaGetSymbolAddress((void**)&QP, g_qpart);
    cudaGetSymbolAddress((void**)&Cc, g_c);

    // q = red_w^T @ proj_w (e-split x2), c = red_b . proj_w + proj_b
    prep_q<<<8, 256>>>(red_w, red_b, proj_w, proj_b, QP, Cc);
    // fused caption mean/l2norm/softmax-w/t + image pooling
    pre_reduce<<<BC + BI, 256>>>(cap, lens, img, conv_b, QP, Cc, capV, W, T_, P);
    // CC = P @ conv_w^T   (768 x 1024, K=1024): 16 x 24 = 384 blocks
    gemm_s<<<dim3(DD / 64, (BI * 3) / 32, 1), 128>>>(P, conv_w, CC, BI * 3, DD, DD, DD);
    // S = CC @ cap_v^T    (768 x 256, K=1024): 4 x 24 x 4 = 384 blocks, split-K
    gemm_s<<<dim3(BC / 64, (BI * 3) / 32, KSPLIT), 128>>>(CC, capV, SP, BI * 3, BC, DD, KC);
    // fused Gram + split-K sum + final similarity
    final_kernel<<<BI, 256>>>(CC, conv_b, SP, W, T_, out);
}